// round 3
// baseline (speedup 1.0000x reference)
#include <cuda_runtime.h>

#define NND  30000
#define NE   960000
#define IND  4527
#define HOGD 4464
#define NG   64

// ---------------- scratch (static __device__ arrays; no allocation) ----------------
__device__ float g_a[NND * 2];          // per-node attention gate (a0, a1)
__device__ float g_h1[NND * 256];       // GAT1 pre-aggregation features
__device__ float g_as1[NND * 2];        // alpha_src head0/1
__device__ float g_ad1[NND * 2];        // alpha_dst head0/1
__device__ int   g_cnt[NND];
__device__ int   g_rowptr[NND + 1];
__device__ int   g_fill[NND];
__device__ int   g_ssrc[NE];            // edge srcs sorted by dst (CSR)
__device__ float g_hr[NND * 256];       // relu(out1 + b1)  (GAT2 input)
__device__ float g_h2[NND * 128];       // GAT2 pre-aggregation features
__device__ float g_as2[NND];
__device__ float g_ad2[NND];
__device__ float g_o2[NND * 128];       // relu(out2 + b2)
__device__ float g_pool[NG * 128];
__device__ int   g_gstart[NG + 1];

// ---------------- helpers ----------------
__device__ __forceinline__ unsigned f2tf(float f) {
    unsigned r;
    asm("cvt.rna.tf32.f32 %0, %1;" : "=r"(r) : "f"(f));
    return r;
}
__device__ __forceinline__ void mma_tf32(float d[4], const unsigned a[4], const unsigned b[2]) {
    asm volatile(
        "mma.sync.aligned.m16n8k8.row.col.f32.tf32.tf32.f32 "
        "{%0,%1,%2,%3}, {%4,%5,%6,%7}, {%8,%9}, {%0,%1,%2,%3};"
        : "+f"(d[0]), "+f"(d[1]), "+f"(d[2]), "+f"(d[3])
        : "r"(a[0]), "r"(a[1]), "r"(a[2]), "r"(a[3]), "r"(b[0]), "r"(b[1]));
}

// ---------------- per-node input attention softmax ----------------
__global__ void k_attn(const float* __restrict__ x, const float* __restrict__ aw,
                       const float* __restrict__ ab) {
    int w = (blockIdx.x * blockDim.x + threadIdx.x) >> 5;
    if (w >= NND) return;
    int lane = threadIdx.x & 31;
    const float* xr = x + (size_t)w * IND;
    float l0 = 0.f, l1 = 0.f;
    for (int k = lane; k < IND; k += 32) {
        float v = xr[k];
        l0 += v * aw[k * 2 + 0];
        l1 += v * aw[k * 2 + 1];
    }
#pragma unroll
    for (int o = 16; o; o >>= 1) {
        l0 += __shfl_xor_sync(0xffffffffu, l0, o);
        l1 += __shfl_xor_sync(0xffffffffu, l1, o);
    }
    if (lane == 0) {
        l0 += ab[0]; l1 += ab[1];
        float m = fmaxf(l0, l1);
        float e0 = __expf(l0 - m), e1 = __expf(l1 - m);
        float inv = 1.f / (e0 + e1);
        g_a[w * 2 + 0] = e0 * inv;
        g_a[w * 2 + 1] = e1 * inv;
    }
}

// ---------------- CSR build: zero / hist / scan / scatter ----------------
__global__ void k_zero() {
    int i = blockIdx.x * blockDim.x + threadIdx.x;
    if (i < NND) { g_cnt[i] = 0; g_fill[i] = 0; }
}
__global__ void k_hist(const int* __restrict__ dst) {
    int i = blockIdx.x * blockDim.x + threadIdx.x;
    if (i < NE) atomicAdd(&g_cnt[dst[i]], 1);
}
__global__ void k_scan() {  // single block, 1024 threads, chunked Hillis-Steele
    __shared__ int s[1024];
    __shared__ int csh;
    int tid = threadIdx.x;
    if (tid == 0) csh = 0;
    __syncthreads();
    for (int base = 0; base < NND; base += 1024) {
        int i = base + tid;
        int v = (i < NND) ? g_cnt[i] : 0;
        s[tid] = v;
        __syncthreads();
        for (int off = 1; off < 1024; off <<= 1) {
            int t = (tid >= off) ? s[tid - off] : 0;
            __syncthreads();
            s[tid] += t;
            __syncthreads();
        }
        if (i < NND) g_rowptr[i] = csh + s[tid] - v;
        int tot = s[1023];
        __syncthreads();
        if (tid == 0) csh += tot;
        __syncthreads();
    }
    if (tid == 0) g_rowptr[NND] = csh;
}
__global__ void k_scatter(const int* __restrict__ src, const int* __restrict__ dst) {
    int i = blockIdx.x * blockDim.x + threadIdx.x;
    if (i < NE) {
        int d = dst[i];
        int pos = g_rowptr[d] + atomicAdd(&g_fill[d], 1);
        g_ssrc[pos] = src[i];
    }
}

// ---------------- tf32 tensor-core GEMM ----------------
// MODE 0: A = x (scaled by attention gate per k-region), C = g_h1, K=4527, Nfull=256
// MODE 1: A = g_hr, C = g_h2, K=256, Nfull=128
// BM=128, BN=128, BK=16, 256 threads (8 warps: 2 in M x 4 in N, warp tile 64x32)
template <int MODE>
__global__ __launch_bounds__(256) void k_gemm_tc(const float* __restrict__ Aglob,
                                                 const float* __restrict__ B) {
    constexpr int Kdim  = (MODE == 0) ? IND : 256;
    constexpr int Nfull = (MODE == 0) ? 256 : 128;
    constexpr int M = NND;
    const float* A = (MODE == 0) ? Aglob : g_hr;
    float* C = (MODE == 0) ? g_h1 : g_h2;

    __shared__ float As[2][128][20];    // stride 20 -> conflict-free fragment reads
    __shared__ float Bs[2][16][136];    // stride 136 -> conflict-free fragment reads

    const int tid  = threadIdx.x;
    const int lane = tid & 31;
    const int warp = tid >> 5;
    const int wm = warp & 1;            // 0..1 -> m offset wm*64
    const int wn = warp >> 1;           // 0..3 -> n offset wn*32
    const int m0 = blockIdx.y * 128;
    const int n0 = blockIdx.x * 128;

    // global->smem load mapping
    const int ar = tid >> 2;            // row within tile half (0..63)
    const int ak = (tid & 3) * 4;       // k chunk start (0,4,8,12)
    const int bk = tid >> 5;            // B k-row (0..7, plus +8)
    const int bn = (tid & 31) * 4;      // B n chunk

    float d[4][4][4];
#pragma unroll
    for (int i = 0; i < 4; i++)
#pragma unroll
        for (int j = 0; j < 4; j++)
#pragma unroll
            for (int c = 0; c < 4; c++) d[i][j][c] = 0.f;

    const int nsteps = (Kdim + 15) / 16;

    float ra[2][4];
    float4 rb[2];

    // ---- fetch k-chunk 0 ----
#pragma unroll
    for (int i = 0; i < 2; i++) {
        int r = m0 + ar + i * 64;
        float s0 = 1.f, s1 = 1.f;
        if (MODE == 0 && r < M) { s0 = g_a[r * 2]; s1 = g_a[r * 2 + 1]; }
#pragma unroll
        for (int j = 0; j < 4; j++) {
            int k = ak + j;
            float v = (r < M && k < Kdim) ? A[(size_t)r * Kdim + k] : 0.f;
            if (MODE == 0) v *= (k < HOGD) ? s0 : s1;
            ra[i][j] = v;
        }
    }
#pragma unroll
    for (int i = 0; i < 2; i++) {
        int k = bk + i * 8;
        rb[i] = (k < Kdim) ? *(const float4*)(B + (size_t)k * Nfull + n0 + bn)
                           : make_float4(0.f, 0.f, 0.f, 0.f);
    }
#pragma unroll
    for (int i = 0; i < 2; i++)
#pragma unroll
        for (int j = 0; j < 4; j++) As[0][ar + i * 64][ak + j] = ra[i][j];
#pragma unroll
    for (int i = 0; i < 2; i++) *(float4*)&Bs[0][bk + i * 8][bn] = rb[i];
    __syncthreads();

    for (int s = 0; s < nsteps; s++) {
        const int st = s & 1;
        const bool has = (s + 1 < nsteps);
        const int k0n = (s + 1) * 16;
        // prefetch next chunk into regs (overlaps with compute)
        if (has) {
#pragma unroll
            for (int i = 0; i < 2; i++) {
                int r = m0 + ar + i * 64;
                float s0 = 1.f, s1 = 1.f;
                if (MODE == 0 && r < M) { s0 = g_a[r * 2]; s1 = g_a[r * 2 + 1]; }
#pragma unroll
                for (int j = 0; j < 4; j++) {
                    int k = k0n + ak + j;
                    float v = (r < M && k < Kdim) ? A[(size_t)r * Kdim + k] : 0.f;
                    if (MODE == 0) v *= (k < HOGD) ? s0 : s1;
                    ra[i][j] = v;
                }
            }
#pragma unroll
            for (int i = 0; i < 2; i++) {
                int k = k0n + bk + i * 8;
                rb[i] = (k < Kdim) ? *(const float4*)(B + (size_t)k * Nfull + n0 + bn)
                                   : make_float4(0.f, 0.f, 0.f, 0.f);
            }
        }
        // compute on current stage: two k8 sub-steps
#pragma unroll
        for (int kk = 0; kk < 16; kk += 8) {
            unsigned af[4][4], bf[4][2];
#pragma unroll
            for (int am = 0; am < 4; am++) {
                int mb = wm * 64 + am * 16 + (lane >> 2);
                int kc = kk + (lane & 3);
                af[am][0] = f2tf(As[st][mb][kc]);
                af[am][1] = f2tf(As[st][mb + 8][kc]);
                af[am][2] = f2tf(As[st][mb][kc + 4]);
                af[am][3] = f2tf(As[st][mb + 8][kc + 4]);
            }
#pragma unroll
            for (int an = 0; an < 4; an++) {
                int nb = wn * 32 + an * 8 + (lane >> 2);
                bf[an][0] = f2tf(Bs[st][kk + (lane & 3)][nb]);
                bf[an][1] = f2tf(Bs[st][kk + 4 + (lane & 3)][nb]);
            }
#pragma unroll
            for (int am = 0; am < 4; am++)
#pragma unroll
                for (int an = 0; an < 4; an++) mma_tf32(d[am][an], af[am], bf[an]);
        }
        // write next stage
        if (has) {
            const int nx = st ^ 1;
#pragma unroll
            for (int i = 0; i < 2; i++)
#pragma unroll
                for (int j = 0; j < 4; j++) As[nx][ar + i * 64][ak + j] = ra[i][j];
#pragma unroll
            for (int i = 0; i < 2; i++) *(float4*)&Bs[nx][bk + i * 8][bn] = rb[i];
        }
        __syncthreads();
    }

    // epilogue
#pragma unroll
    for (int am = 0; am < 4; am++) {
        int row = m0 + wm * 64 + am * 16 + (lane >> 2);
#pragma unroll
        for (int an = 0; an < 4; an++) {
            int col = n0 + wn * 32 + an * 8 + (lane & 3) * 2;
            if (row < M)
                *(float2*)&C[(size_t)row * Nfull + col] = make_float2(d[am][an][0], d[am][an][1]);
            if (row + 8 < M)
                *(float2*)&C[(size_t)(row + 8) * Nfull + col] = make_float2(d[am][an][2], d[am][an][3]);
        }
    }
}

// ---------------- per-node alpha dot products ----------------
__global__ void k_alpha1(const float* __restrict__ asrc, const float* __restrict__ adst) {
    int w = (blockIdx.x * blockDim.x + threadIdx.x) >> 5;
    if (w >= NND) return;
    int lane = threadIdx.x & 31;
    const float* hp = g_h1 + (size_t)w * 256;
    float s0 = 0, d0 = 0, s1 = 0, d1 = 0;
#pragma unroll
    for (int r = 0; r < 8; r++) {
        int f = lane + 32 * r;
        float v = hp[f];
        float wa = asrc[f], wd = adst[f];
        if (r < 4) { s0 += v * wa; d0 += v * wd; }
        else       { s1 += v * wa; d1 += v * wd; }
    }
#pragma unroll
    for (int o = 16; o; o >>= 1) {
        s0 += __shfl_xor_sync(0xffffffffu, s0, o);
        d0 += __shfl_xor_sync(0xffffffffu, d0, o);
        s1 += __shfl_xor_sync(0xffffffffu, s1, o);
        d1 += __shfl_xor_sync(0xffffffffu, d1, o);
    }
    if (lane == 0) {
        g_as1[w * 2] = s0; g_as1[w * 2 + 1] = s1;
        g_ad1[w * 2] = d0; g_ad1[w * 2 + 1] = d1;
    }
}
__global__ void k_alpha2(const float* __restrict__ asrc, const float* __restrict__ adst) {
    int w = (blockIdx.x * blockDim.x + threadIdx.x) >> 5;
    if (w >= NND) return;
    int lane = threadIdx.x & 31;
    const float* hp = g_h2 + (size_t)w * 128;
    float s0 = 0, d0 = 0;
#pragma unroll
    for (int r = 0; r < 4; r++) {
        int f = lane + 32 * r;
        float v = hp[f];
        s0 += v * asrc[f];
        d0 += v * adst[f];
    }
#pragma unroll
    for (int o = 16; o; o >>= 1) {
        s0 += __shfl_xor_sync(0xffffffffu, s0, o);
        d0 += __shfl_xor_sync(0xffffffffu, d0, o);
    }
    if (lane == 0) { g_as2[w] = s0; g_ad2[w] = d0; }
}

// ---------------- GAT1 edge-softmax + aggregation (warp per dst) ----------------
__global__ void k_agg1(const float* __restrict__ b1) {
    int d = (blockIdx.x * blockDim.x + threadIdx.x) >> 5;
    if (d >= NND) return;
    int lane = threadIdx.x & 31;
    int beg = g_rowptr[d], end = g_rowptr[d + 1];
    int deg = end - beg;
    int total = deg + 1;  // + self loop
    float ad0 = g_ad1[d * 2], ad1 = g_ad1[d * 2 + 1];
    float m0 = -1e30f, m1 = -1e30f;
    for (int i = lane; i < total; i += 32) {
        int s = (i < deg) ? g_ssrc[beg + i] : d;
        float e0 = g_as1[s * 2] + ad0;     e0 = e0 > 0.f ? e0 : 0.2f * e0;
        float e1 = g_as1[s * 2 + 1] + ad1; e1 = e1 > 0.f ? e1 : 0.2f * e1;
        m0 = fmaxf(m0, e0); m1 = fmaxf(m1, e1);
    }
#pragma unroll
    for (int o = 16; o; o >>= 1) {
        m0 = fmaxf(m0, __shfl_xor_sync(0xffffffffu, m0, o));
        m1 = fmaxf(m1, __shfl_xor_sync(0xffffffffu, m1, o));
    }
    float acc[8] = {0, 0, 0, 0, 0, 0, 0, 0};
    float ws0 = 0.f, ws1 = 0.f;
    for (int base = 0; base < total; base += 32) {
        int i = base + lane;
        float w0 = 0.f, w1 = 0.f;
        int s = d;
        if (i < total) {
            s = (i < deg) ? g_ssrc[beg + i] : d;
            float e0 = g_as1[s * 2] + ad0;     e0 = e0 > 0.f ? e0 : 0.2f * e0;
            float e1 = g_as1[s * 2 + 1] + ad1; e1 = e1 > 0.f ? e1 : 0.2f * e1;
            w0 = __expf(e0 - m0); w1 = __expf(e1 - m1);
            ws0 += w0; ws1 += w1;
        }
        int cnt = min(32, total - base);
        for (int j = 0; j < cnt; j++) {
            int   sj  = __shfl_sync(0xffffffffu, s, j);
            float w0j = __shfl_sync(0xffffffffu, w0, j);
            float w1j = __shfl_sync(0xffffffffu, w1, j);
            const float4* hp = (const float4*)(g_h1 + (size_t)sj * 256);
            float4 v0 = hp[lane * 2], v1 = hp[lane * 2 + 1];
            float ww = (lane < 16) ? w0j : w1j;   // lane owns feats lane*8..+7
            acc[0] += ww * v0.x; acc[1] += ww * v0.y; acc[2] += ww * v0.z; acc[3] += ww * v0.w;
            acc[4] += ww * v1.x; acc[5] += ww * v1.y; acc[6] += ww * v1.z; acc[7] += ww * v1.w;
        }
    }
#pragma unroll
    for (int o = 16; o; o >>= 1) {
        ws0 += __shfl_xor_sync(0xffffffffu, ws0, o);
        ws1 += __shfl_xor_sync(0xffffffffu, ws1, o);
    }
    float inv = (lane < 16) ? (1.f / (ws0 + 1e-16f)) : (1.f / (ws1 + 1e-16f));
    float out[8];
#pragma unroll
    for (int r = 0; r < 8; r++)
        out[r] = fmaxf(acc[r] * inv + b1[lane * 8 + r], 0.f);
    float4* op = (float4*)(g_hr + (size_t)d * 256 + lane * 8);
    op[0] = make_float4(out[0], out[1], out[2], out[3]);
    op[1] = make_float4(out[4], out[5], out[6], out[7]);
}

// ---------------- GAT2 edge-softmax + aggregation (warp per dst, 1 head) -----------
__global__ void k_agg2(const float* __restrict__ b2) {
    int d = (blockIdx.x * blockDim.x + threadIdx.x) >> 5;
    if (d >= NND) return;
    int lane = threadIdx.x & 31;
    int beg = g_rowptr[d], end = g_rowptr[d + 1];
    int deg = end - beg;
    int total = deg + 1;
    float ad0 = g_ad2[d];
    float m0 = -1e30f;
    for (int i = lane; i < total; i += 32) {
        int s = (i < deg) ? g_ssrc[beg + i] : d;
        float e0 = g_as2[s] + ad0; e0 = e0 > 0.f ? e0 : 0.2f * e0;
        m0 = fmaxf(m0, e0);
    }
#pragma unroll
    for (int o = 16; o; o >>= 1) m0 = fmaxf(m0, __shfl_xor_sync(0xffffffffu, m0, o));
    float acc[4] = {0, 0, 0, 0};
    float ws0 = 0.f;
    for (int base = 0; base < total; base += 32) {
        int i = base + lane;
        float w0 = 0.f;
        int s = d;
        if (i < total) {
            s = (i < deg) ? g_ssrc[beg + i] : d;
            float e0 = g_as2[s] + ad0; e0 = e0 > 0.f ? e0 : 0.2f * e0;
            w0 = __expf(e0 - m0);
            ws0 += w0;
        }
        int cnt = min(32, total - base);
        for (int j = 0; j < cnt; j++) {
            int   sj  = __shfl_sync(0xffffffffu, s, j);
            float w0j = __shfl_sync(0xffffffffu, w0, j);
            float4 v = ((const float4*)(g_h2 + (size_t)sj * 128))[lane];
            acc[0] += w0j * v.x; acc[1] += w0j * v.y; acc[2] += w0j * v.z; acc[3] += w0j * v.w;
        }
    }
#pragma unroll
    for (int o = 16; o; o >>= 1) ws0 += __shfl_xor_sync(0xffffffffu, ws0, o);
    float inv = 1.f / (ws0 + 1e-16f);
    float out[4];
#pragma unroll
    for (int r = 0; r < 4; r++)
        out[r] = fmaxf(acc[r] * inv + b2[lane * 4 + r], 0.f);
    ((float4*)(g_o2 + (size_t)d * 128))[lane] = make_float4(out[0], out[1], out[2], out[3]);
}

// ---------------- pooling + MLP head ----------------
__global__ void k_gstart(const int* __restrict__ batch) {
    int g = threadIdx.x;
    if (g > NG) return;
    int lo = 0, hi = NND;
    while (lo < hi) {
        int mid = (lo + hi) >> 1;
        if (batch[mid] < g) lo = mid + 1; else hi = mid;
    }
    g_gstart[g] = lo;
}
__global__ void k_pool() {
    int g = blockIdx.x;
    int f = threadIdx.x;
    int s = g_gstart[g], e = g_gstart[g + 1];
    float acc = 0.f;
    for (int n = s; n < e; n++) acc += g_o2[(size_t)n * 128 + f];
    float c = (float)max(e - s, 1);
    g_pool[g * 128 + f] = acc / c;
}
__global__ void k_mlp(const float* __restrict__ Wc1, const float* __restrict__ bc1,
                      const float* __restrict__ Wc2, const float* __restrict__ bc2,
                      float* __restrict__ out) {
    __shared__ float z[64 * 64];
    int tid = threadIdx.x;
    for (int idx = tid; idx < 64 * 64; idx += blockDim.x) {
        int i = idx >> 6, j = idx & 63;
        float acc = bc1[j];
        const float* p = g_pool + i * 128;
        for (int k = 0; k < 128; k++) acc += p[k] * Wc1[k * 64 + j];
        z[idx] = fmaxf(acc, 0.f);
    }
    __syncthreads();
    for (int idx = tid; idx < NG * 4; idx += blockDim.x) {
        int i = idx >> 2, c = idx & 3;
        float acc = bc2[c];
        for (int k = 0; k < 64; k++) acc += z[i * 64 + k] * Wc2[k * 4 + c];
        out[idx] = acc;
    }
}

// ---------------- launch ----------------
extern "C" void kernel_launch(void* const* d_in, const int* in_sizes, int n_in,
                              void* d_out, int out_size) {
    const float* x      = (const float*)d_in[0];
    const int*   ei     = (const int*)d_in[1];
    const int*   batch  = (const int*)d_in[2];
    const float* attn_W = (const float*)d_in[3];
    const float* attn_b = (const float*)d_in[4];
    const float* W1     = (const float*)d_in[5];
    const float* a_src1 = (const float*)d_in[6];
    const float* a_dst1 = (const float*)d_in[7];
    const float* b1     = (const float*)d_in[8];
    const float* W2     = (const float*)d_in[9];
    const float* a_src2 = (const float*)d_in[10];
    const float* a_dst2 = (const float*)d_in[11];
    const float* b2     = (const float*)d_in[12];
    const float* Wc1    = (const float*)d_in[13];
    const float* bc1    = (const float*)d_in[14];
    const float* Wc2    = (const float*)d_in[15];
    const float* bc2    = (const float*)d_in[16];
    float* out = (float*)d_out;

    const int WARP_BLOCKS = (NND * 32 + 255) / 256;   // warp-per-node kernels
    const int EDGE_BLOCKS = (NE + 255) / 256;
    const int MB = (NND + 127) / 128;                 // 235

    k_attn<<<WARP_BLOCKS, 256>>>(x, attn_W, attn_b);
    k_zero<<<(NND + 255) / 256, 256>>>();
    k_hist<<<EDGE_BLOCKS, 256>>>(ei + NE);
    k_scan<<<1, 1024>>>();
    k_scatter<<<EDGE_BLOCKS, 256>>>(ei, ei + NE);

    k_gemm_tc<0><<<dim3(2, MB), 256>>>(x, W1);        // 30000x256 = a-scaled x @ W1
    k_alpha1<<<WARP_BLOCKS, 256>>>(a_src1, a_dst1);
    k_agg1<<<WARP_BLOCKS, 256>>>(b1);

    k_gemm_tc<1><<<dim3(1, MB), 256>>>(nullptr, W2);  // 30000x128 = g_hr @ W2
    k_alpha2<<<WARP_BLOCKS, 256>>>(a_src2, a_dst2);
    k_agg2<<<WARP_BLOCKS, 256>>>(b2);

    k_gstart<<<1, 128>>>(batch);
    k_pool<<<NG, 128>>>();
    k_mlp<<<1, 256>>>(Wc1, bc1, Wc2, bc2, out);
}

// round 4
// speedup vs baseline: 1.0123x; 1.0123x over previous
#include <cuda_runtime.h>

#define NND  30000
#define NE   960000
#define IND  4527
#define HOGD 4464
#define NG   64
#define NBLK 30              // ceil(NND/1024)

// ---------------- scratch (static __device__ arrays; no allocation) ----------------
__device__ float g_h1[NND * 256];       // cov-part Q, then final GAT1 pre-agg features
__device__ float g_lcov[NND * 2];       // cov contribution to attention logits
__device__ float g_as1[NND * 2];        // alpha_src head0/1
__device__ float g_ad1[NND * 2];        // alpha_dst head0/1
__device__ int   g_cnt[NND];
__device__ int   g_pscan[NND];
__device__ int   g_btot[32];
__device__ int   g_boff[32];
__device__ int   g_rowptr[NND + 1];
__device__ int   g_fill[NND];
__device__ int   g_ssrc[NE];            // edge srcs sorted by dst (CSR)
__device__ float g_hr[NND * 256];       // relu(out1 + b1)  (GAT2 input)
__device__ float g_h2[NND * 128];       // GAT2 pre-aggregation features
__device__ float g_as2[NND];
__device__ float g_ad2[NND];
__device__ float g_o2[NND * 128];       // relu(out2 + b2)
__device__ float g_pool[NG * 128];
__device__ int   g_gstart[NG + 1];

// ---------------- helpers ----------------
__device__ __forceinline__ unsigned f2tf(float f) {
    unsigned r;
    asm("cvt.rna.tf32.f32 %0, %1;" : "=r"(r) : "f"(f));
    return r;
}
__device__ __forceinline__ void mma_tf32(float d[4], const unsigned a[4], const unsigned b[2]) {
    asm volatile(
        "mma.sync.aligned.m16n8k8.row.col.f32.tf32.tf32.f32 "
        "{%0,%1,%2,%3}, {%4,%5,%6,%7}, {%8,%9}, {%0,%1,%2,%3};"
        : "+f"(d[0]), "+f"(d[1]), "+f"(d[2]), "+f"(d[3])
        : "r"(a[0]), "r"(a[1]), "r"(a[2]), "r"(a[3]), "r"(b[0]), "r"(b[1]));
}

// ---------------- cov mini-GEMM: Q = cov @ W1_cov, plus cov logit partials ---------
__global__ void k_cov(const float* __restrict__ x, const float* __restrict__ W1,
                      const float* __restrict__ aw) {
    int w = (blockIdx.x * blockDim.x + threadIdx.x) >> 5;
    if (w >= NND) return;
    int lane = threadIdx.x & 31;
    const float* xr = x + (size_t)w * IND + HOGD;   // 63 cov values
    float c0 = xr[lane];                            // lanes 0..31 (< 63)
    float c1 = (lane + 32 < IND - HOGD) ? xr[lane + 32] : 0.f;

    // cov part of attention logits
    float l0 = c0 * aw[(HOGD + lane) * 2]     + c1 * aw[(HOGD + lane + 32) * 2];
    float l1 = c0 * aw[(HOGD + lane) * 2 + 1] + c1 * aw[(HOGD + lane + 32) * 2 + 1];
#pragma unroll
    for (int o = 16; o; o >>= 1) {
        l0 += __shfl_xor_sync(0xffffffffu, l0, o);
        l1 += __shfl_xor_sync(0xffffffffu, l1, o);
    }
    if (lane == 0) { g_lcov[w * 2] = l0; g_lcov[w * 2 + 1] = l1; }

    // Q = cov @ W1[HOGD:, :], lane owns cols lane*8..+7
    float acc[8] = {0, 0, 0, 0, 0, 0, 0, 0};
    for (int k = 0; k < IND - HOGD; k++) {
        float v = (k < 32) ? __shfl_sync(0xffffffffu, c0, k)
                           : __shfl_sync(0xffffffffu, c1, k - 32);
        const float4* wr = (const float4*)(W1 + (size_t)(HOGD + k) * 256 + lane * 8);
        float4 w0 = wr[0], w1 = wr[1];
        acc[0] += v * w0.x; acc[1] += v * w0.y; acc[2] += v * w0.z; acc[3] += v * w0.w;
        acc[4] += v * w1.x; acc[5] += v * w1.y; acc[6] += v * w1.z; acc[7] += v * w1.w;
    }
    float4* qp = (float4*)(g_h1 + (size_t)w * 256 + lane * 8);
    qp[0] = make_float4(acc[0], acc[1], acc[2], acc[3]);
    qp[1] = make_float4(acc[4], acc[5], acc[6], acc[7]);
}

// ---------------- CSR build: zero / hist / 3-kernel scan / scatter ----------------
__global__ void k_zero() {
    int i = blockIdx.x * blockDim.x + threadIdx.x;
    if (i < NND) { g_cnt[i] = 0; g_fill[i] = 0; }
}
__global__ void k_hist(const int* __restrict__ dst) {
    int i = blockIdx.x * blockDim.x + threadIdx.x;
    if (i < NE) atomicAdd(&g_cnt[dst[i]], 1);
}
__global__ void k_scan1() {
    __shared__ int wsum[32];
    int b = blockIdx.x, tid = threadIdx.x;
    int lane = tid & 31, wq = tid >> 5;
    int i = b * 1024 + tid;
    int v = (i < NND) ? g_cnt[i] : 0;
    int incl = v;
#pragma unroll
    for (int o = 1; o < 32; o <<= 1) {
        int t = __shfl_up_sync(0xffffffffu, incl, o);
        if (lane >= o) incl += t;
    }
    if (lane == 31) wsum[wq] = incl;
    __syncthreads();
    if (wq == 0) {
        int s = wsum[lane];
#pragma unroll
        for (int o = 1; o < 32; o <<= 1) {
            int t = __shfl_up_sync(0xffffffffu, s, o);
            if (lane >= o) s += t;
        }
        wsum[lane] = s;
    }
    __syncthreads();
    int woff = (wq > 0) ? wsum[wq - 1] : 0;
    if (i < NND) g_pscan[i] = incl + woff - v;     // exclusive within block
    if (tid == 0) g_btot[b] = wsum[31];
}
__global__ void k_scan2() {
    int lane = threadIdx.x;
    int v = (lane < NBLK) ? g_btot[lane] : 0;
    int incl = v;
#pragma unroll
    for (int o = 1; o < 32; o <<= 1) {
        int t = __shfl_up_sync(0xffffffffu, incl, o);
        if (lane >= o) incl += t;
    }
    if (lane < NBLK) g_boff[lane] = incl - v;
}
__global__ void k_scan3() {
    int i = blockIdx.x * blockDim.x + threadIdx.x;
    if (i < NND) g_rowptr[i] = g_pscan[i] + g_boff[i >> 10];
    if (i == 0) g_rowptr[NND] = NE;
}
__global__ void k_scatter(const int* __restrict__ src, const int* __restrict__ dst) {
    int i = blockIdx.x * blockDim.x + threadIdx.x;
    if (i < NE) {
        int d = dst[i];
        int pos = g_rowptr[d] + atomicAdd(&g_fill[d], 1);
        g_ssrc[pos] = src[i];
    }
}

// ---------------- tf32 tensor-core GEMM ----------------
// MODE 0: A = x (raw hog region K=4464), fused logit accumulation + gate at epilogue:
//         g_h1 = a0 * (hog@W1_hog) + a1 * Q   (Q precomputed by k_cov into g_h1)
// MODE 1: A = g_hr, C = g_h2, K=256, Nfull=128
// BM=128, BN=128, BK=16, 256 threads (8 warps: 2 in M x 4 in N, warp tile 64x32)
template <int MODE>
__global__ __launch_bounds__(256) void k_gemm_tc(const float* __restrict__ Aglob,
                                                 const float* __restrict__ B,
                                                 const float* __restrict__ aw,
                                                 const float* __restrict__ ab) {
    constexpr int Kdim  = (MODE == 0) ? HOGD : 256;   // 4464 = 279*16 exactly
    constexpr int Astr  = (MODE == 0) ? IND  : 256;   // A row stride
    constexpr int Nfull = (MODE == 0) ? 256 : 128;
    constexpr int M = NND;
    const float* A = (MODE == 0) ? Aglob : g_hr;
    float* C = (MODE == 0) ? g_h1 : g_h2;

    __shared__ unsigned As[2][128][20];   // tf32-converted, stride 20: conflict-free
    __shared__ unsigned Bs[2][16][136];   // tf32-converted, stride 136: conflict-free
    __shared__ float ssa0[128], ssa1[128];

    const int tid  = threadIdx.x;
    const int lane = tid & 31;
    const int warp = tid >> 5;
    const int wm = warp & 1;
    const int wn = warp >> 1;
    const int m0 = blockIdx.y * 128;
    const int n0 = blockIdx.x * 128;

    const int ar = tid >> 2;            // A row within half (0..63)
    const int ak = (tid & 3) * 4;       // A k chunk (0,4,8,12)
    const int bk = tid >> 5;            // B k row (0..7, +8)
    const int bn = (tid & 31) * 4;      // B n chunk

    float d[4][4][4];
#pragma unroll
    for (int i = 0; i < 4; i++)
#pragma unroll
        for (int j = 0; j < 4; j++)
#pragma unroll
            for (int c = 0; c < 4; c++) d[i][j][c] = 0.f;

    float lp[2][2] = {{0.f, 0.f}, {0.f, 0.f}};   // logit partials [row half][head]

    constexpr int nsteps = Kdim / 16;
    float ra[2][4];
    float4 rb[2];

    // ---- fetch k-chunk 0 ----
#pragma unroll
    for (int i = 0; i < 2; i++) {
        int r = m0 + ar + i * 64;
#pragma unroll
        for (int j = 0; j < 4; j++) {
            int k = ak + j;
            float v = (r < M) ? A[(size_t)r * Astr + k] : 0.f;
            ra[i][j] = v;
            if (MODE == 0) {
                lp[i][0] += v * __ldg(&aw[k * 2]);
                lp[i][1] += v * __ldg(&aw[k * 2 + 1]);
            }
        }
    }
#pragma unroll
    for (int i = 0; i < 2; i++)
        rb[i] = *(const float4*)(B + (size_t)(bk + i * 8) * Nfull + n0 + bn);
#pragma unroll
    for (int i = 0; i < 2; i++)
#pragma unroll
        for (int j = 0; j < 4; j++) As[0][ar + i * 64][ak + j] = f2tf(ra[i][j]);
#pragma unroll
    for (int i = 0; i < 2; i++) {
        Bs[0][bk + i * 8][bn]     = f2tf(rb[i].x);
        Bs[0][bk + i * 8][bn + 1] = f2tf(rb[i].y);
        Bs[0][bk + i * 8][bn + 2] = f2tf(rb[i].z);
        Bs[0][bk + i * 8][bn + 3] = f2tf(rb[i].w);
    }
    __syncthreads();

    for (int s = 0; s < nsteps; s++) {
        const int st = s & 1;
        const bool has = (s + 1 < nsteps);
        const int k0n = (s + 1) * 16;
        if (has) {
#pragma unroll
            for (int i = 0; i < 2; i++) {
                int r = m0 + ar + i * 64;
#pragma unroll
                for (int j = 0; j < 4; j++) {
                    int k = k0n + ak + j;
                    float v = (r < M) ? A[(size_t)r * Astr + k] : 0.f;
                    ra[i][j] = v;
                    if (MODE == 0) {
                        lp[i][0] += v * __ldg(&aw[k * 2]);
                        lp[i][1] += v * __ldg(&aw[k * 2 + 1]);
                    }
                }
            }
#pragma unroll
            for (int i = 0; i < 2; i++)
                rb[i] = *(const float4*)(B + (size_t)(k0n + bk + i * 8) * Nfull + n0 + bn);
        }
        // compute current stage: two k8 sub-steps, pure LDS + HMMA
#pragma unroll
        for (int kk = 0; kk < 16; kk += 8) {
            unsigned af[4][4], bf[4][2];
#pragma unroll
            for (int am = 0; am < 4; am++) {
                int mb = wm * 64 + am * 16 + (lane >> 2);
                int kc = kk + (lane & 3);
                af[am][0] = As[st][mb][kc];
                af[am][1] = As[st][mb + 8][kc];
                af[am][2] = As[st][mb][kc + 4];
                af[am][3] = As[st][mb + 8][kc + 4];
            }
#pragma unroll
            for (int an = 0; an < 4; an++) {
                int nb = wn * 32 + an * 8 + (lane >> 2);
                bf[an][0] = Bs[st][kk + (lane & 3)][nb];
                bf[an][1] = Bs[st][kk + 4 + (lane & 3)][nb];
            }
#pragma unroll
            for (int am = 0; am < 4; am++)
#pragma unroll
                for (int an = 0; an < 4; an++) mma_tf32(d[am][an], af[am], bf[an]);
        }
        if (has) {
            const int nx = st ^ 1;
#pragma unroll
            for (int i = 0; i < 2; i++)
#pragma unroll
                for (int j = 0; j < 4; j++) As[nx][ar + i * 64][ak + j] = f2tf(ra[i][j]);
#pragma unroll
            for (int i = 0; i < 2; i++) {
                Bs[nx][bk + i * 8][bn]     = f2tf(rb[i].x);
                Bs[nx][bk + i * 8][bn + 1] = f2tf(rb[i].y);
                Bs[nx][bk + i * 8][bn + 2] = f2tf(rb[i].z);
                Bs[nx][bk + i * 8][bn + 3] = f2tf(rb[i].w);
            }
        }
        __syncthreads();
    }

    if (MODE == 0) {
        // reduce logit partials across the 4 threads sharing each row (quad in-warp)
#pragma unroll
        for (int o = 1; o <= 2; o <<= 1) {
            lp[0][0] += __shfl_xor_sync(0xffffffffu, lp[0][0], o);
            lp[0][1] += __shfl_xor_sync(0xffffffffu, lp[0][1], o);
            lp[1][0] += __shfl_xor_sync(0xffffffffu, lp[1][0], o);
            lp[1][1] += __shfl_xor_sync(0xffffffffu, lp[1][1], o);
        }
        if ((lane & 3) == 0) {
#pragma unroll
            for (int i = 0; i < 2; i++) {
                int lr = ar + i * 64;
                int r = m0 + lr;
                float l0 = lp[i][0], l1 = lp[i][1];
                if (r < M) { l0 += g_lcov[r * 2] + ab[0]; l1 += g_lcov[r * 2 + 1] + ab[1]; }
                float mm = fmaxf(l0, l1);
                float e0 = __expf(l0 - mm), e1 = __expf(l1 - mm);
                float inv = 1.f / (e0 + e1);
                ssa0[lr] = e0 * inv;
                ssa1[lr] = e1 * inv;
            }
        }
        __syncthreads();
    }

    // epilogue
#pragma unroll
    for (int am = 0; am < 4; am++) {
        int lrow = wm * 64 + am * 16 + (lane >> 2);
        int row = m0 + lrow;
#pragma unroll
        for (int an = 0; an < 4; an++) {
            int col = n0 + wn * 32 + an * 8 + (lane & 3) * 2;
            if (MODE == 0) {
                if (row < M) {
                    float a0 = ssa0[lrow], a1 = ssa1[lrow];
                    float2 q = *(float2*)&C[(size_t)row * Nfull + col];
                    *(float2*)&C[(size_t)row * Nfull + col] =
                        make_float2(a0 * d[am][an][0] + a1 * q.x,
                                    a0 * d[am][an][1] + a1 * q.y);
                }
                if (row + 8 < M) {
                    float a0 = ssa0[lrow + 8], a1 = ssa1[lrow + 8];
                    float2 q = *(float2*)&C[(size_t)(row + 8) * Nfull + col];
                    *(float2*)&C[(size_t)(row + 8) * Nfull + col] =
                        make_float2(a0 * d[am][an][2] + a1 * q.x,
                                    a0 * d[am][an][3] + a1 * q.y);
                }
            } else {
                if (row < M)
                    *(float2*)&C[(size_t)row * Nfull + col] =
                        make_float2(d[am][an][0], d[am][an][1]);
                if (row + 8 < M)
                    *(float2*)&C[(size_t)(row + 8) * Nfull + col] =
                        make_float2(d[am][an][2], d[am][an][3]);
            }
        }
    }
}

// ---------------- per-node alpha dot products ----------------
__global__ void k_alpha1(const float* __restrict__ asrc, const float* __restrict__ adst) {
    int w = (blockIdx.x * blockDim.x + threadIdx.x) >> 5;
    if (w >= NND) return;
    int lane = threadIdx.x & 31;
    const float* hp = g_h1 + (size_t)w * 256;
    float s0 = 0, d0 = 0, s1 = 0, d1 = 0;
#pragma unroll
    for (int r = 0; r < 8; r++) {
        int f = lane + 32 * r;
        float v = hp[f];
        float wa = asrc[f], wd = adst[f];
        if (r < 4) { s0 += v * wa; d0 += v * wd; }
        else       { s1 += v * wa; d1 += v * wd; }
    }
#pragma unroll
    for (int o = 16; o; o >>= 1) {
        s0 += __shfl_xor_sync(0xffffffffu, s0, o);
        d0 += __shfl_xor_sync(0xffffffffu, d0, o);
        s1 += __shfl_xor_sync(0xffffffffu, s1, o);
        d1 += __shfl_xor_sync(0xffffffffu, d1, o);
    }
    if (lane == 0) {
        g_as1[w * 2] = s0; g_as1[w * 2 + 1] = s1;
        g_ad1[w * 2] = d0; g_ad1[w * 2 + 1] = d1;
    }
}
__global__ void k_alpha2(const float* __restrict__ asrc, const float* __restrict__ adst) {
    int w = (blockIdx.x * blockDim.x + threadIdx.x) >> 5;
    if (w >= NND) return;
    int lane = threadIdx.x & 31;
    const float* hp = g_h2 + (size_t)w * 128;
    float s0 = 0, d0 = 0;
#pragma unroll
    for (int r = 0; r < 4; r++) {
        int f = lane + 32 * r;
        float v = hp[f];
        s0 += v * asrc[f];
        d0 += v * adst[f];
    }
#pragma unroll
    for (int o = 16; o; o >>= 1) {
        s0 += __shfl_xor_sync(0xffffffffu, s0, o);
        d0 += __shfl_xor_sync(0xffffffffu, d0, o);
    }
    if (lane == 0) { g_as2[w] = s0; g_ad2[w] = d0; }
}

// ---------------- GAT1 edge-softmax + aggregation (warp per dst) ----------------
__global__ void k_agg1(const float* __restrict__ b1) {
    int d = (blockIdx.x * blockDim.x + threadIdx.x) >> 5;
    if (d >= NND) return;
    int lane = threadIdx.x & 31;
    int beg = g_rowptr[d], end = g_rowptr[d + 1];
    int deg = end - beg;
    int total = deg + 1;  // + self loop
    float ad0 = g_ad1[d * 2], ad1 = g_ad1[d * 2 + 1];
    float m0 = -1e30f, m1 = -1e30f;
    for (int i = lane; i < total; i += 32) {
        int s = (i < deg) ? g_ssrc[beg + i] : d;
        float e0 = g_as1[s * 2] + ad0;     e0 = e0 > 0.f ? e0 : 0.2f * e0;
        float e1 = g_as1[s * 2 + 1] + ad1; e1 = e1 > 0.f ? e1 : 0.2f * e1;
        m0 = fmaxf(m0, e0); m1 = fmaxf(m1, e1);
    }
#pragma unroll
    for (int o = 16; o; o >>= 1) {
        m0 = fmaxf(m0, __shfl_xor_sync(0xffffffffu, m0, o));
        m1 = fmaxf(m1, __shfl_xor_sync(0xffffffffu, m1, o));
    }
    float acc[8] = {0, 0, 0, 0, 0, 0, 0, 0};
    float ws0 = 0.f, ws1 = 0.f;
    for (int base = 0; base < total; base += 32) {
        int i = base + lane;
        float w0 = 0.f, w1 = 0.f;
        int s = d;
        if (i < total) {
            s = (i < deg) ? g_ssrc[beg + i] : d;
            float e0 = g_as1[s * 2] + ad0;     e0 = e0 > 0.f ? e0 : 0.2f * e0;
            float e1 = g_as1[s * 2 + 1] + ad1; e1 = e1 > 0.f ? e1 : 0.2f * e1;
            w0 = __expf(e0 - m0); w1 = __expf(e1 - m1);
            ws0 += w0; ws1 += w1;
        }
        int cnt = min(32, total - base);
        for (int j = 0; j < cnt; j++) {
            int   sj  = __shfl_sync(0xffffffffu, s, j);
            float w0j = __shfl_sync(0xffffffffu, w0, j);
            float w1j = __shfl_sync(0xffffffffu, w1, j);
            const float4* hp = (const float4*)(g_h1 + (size_t)sj * 256);
            float4 v0 = hp[lane * 2], v1 = hp[lane * 2 + 1];
            float ww = (lane < 16) ? w0j : w1j;   // lane owns feats lane*8..+7
            acc[0] += ww * v0.x; acc[1] += ww * v0.y; acc[2] += ww * v0.z; acc[3] += ww * v0.w;
            acc[4] += ww * v1.x; acc[5] += ww * v1.y; acc[6] += ww * v1.z; acc[7] += ww * v1.w;
        }
    }
#pragma unroll
    for (int o = 16; o; o >>= 1) {
        ws0 += __shfl_xor_sync(0xffffffffu, ws0, o);
        ws1 += __shfl_xor_sync(0xffffffffu, ws1, o);
    }
    float inv = (lane < 16) ? (1.f / (ws0 + 1e-16f)) : (1.f / (ws1 + 1e-16f));
    float out[8];
#pragma unroll
    for (int r = 0; r < 8; r++)
        out[r] = fmaxf(acc[r] * inv + b1[lane * 8 + r], 0.f);
    float4* op = (float4*)(g_hr + (size_t)d * 256 + lane * 8);
    op[0] = make_float4(out[0], out[1], out[2], out[3]);
    op[1] = make_float4(out[4], out[5], out[6], out[7]);
}

// ---------------- GAT2 edge-softmax + aggregation (warp per dst, 1 head) -----------
__global__ void k_agg2(const float* __restrict__ b2) {
    int d = (blockIdx.x * blockDim.x + threadIdx.x) >> 5;
    if (d >= NND) return;
    int lane = threadIdx.x & 31;
    int beg = g_rowptr[d], end = g_rowptr[d + 1];
    int deg = end - beg;
    int total = deg + 1;
    float ad0 = g_ad2[d];
    float m0 = -1e30f;
    for (int i = lane; i < total; i += 32) {
        int s = (i < deg) ? g_ssrc[beg + i] : d;
        float e0 = g_as2[s] + ad0; e0 = e0 > 0.f ? e0 : 0.2f * e0;
        m0 = fmaxf(m0, e0);
    }
#pragma unroll
    for (int o = 16; o; o >>= 1) m0 = fmaxf(m0, __shfl_xor_sync(0xffffffffu, m0, o));
    float acc[4] = {0, 0, 0, 0};
    float ws0 = 0.f;
    for (int base = 0; base < total; base += 32) {
        int i = base + lane;
        float w0 = 0.f;
        int s = d;
        if (i < total) {
            s = (i < deg) ? g_ssrc[beg + i] : d;
            float e0 = g_as2[s] + ad0; e0 = e0 > 0.f ? e0 : 0.2f * e0;
            w0 = __expf(e0 - m0);
            ws0 += w0;
        }
        int cnt = min(32, total - base);
        for (int j = 0; j < cnt; j++) {
            int   sj  = __shfl_sync(0xffffffffu, s, j);
            float w0j = __shfl_sync(0xffffffffu, w0, j);
            float4 v = ((const float4*)(g_h2 + (size_t)sj * 128))[lane];
            acc[0] += w0j * v.x; acc[1] += w0j * v.y; acc[2] += w0j * v.z; acc[3] += w0j * v.w;
        }
    }
#pragma unroll
    for (int o = 16; o; o >>= 1) ws0 += __shfl_xor_sync(0xffffffffu, ws0, o);
    float inv = 1.f / (ws0 + 1e-16f);
    float out[4];
#pragma unroll
    for (int r = 0; r < 4; r++)
        out[r] = fmaxf(acc[r] * inv + b2[lane * 4 + r], 0.f);
    ((float4*)(g_o2 + (size_t)d * 128))[lane] = make_float4(out[0], out[1], out[2], out[3]);
}

// ---------------- pooling + MLP head ----------------
__global__ void k_gstart(const int* __restrict__ batch) {
    int g = threadIdx.x;
    if (g > NG) return;
    int lo = 0, hi = NND;
    while (lo < hi) {
        int mid = (lo + hi) >> 1;
        if (batch[mid] < g) lo = mid + 1; else hi = mid;
    }
    g_gstart[g] = lo;
}
__global__ void k_pool() {
    int g = blockIdx.x;
    int f = threadIdx.x;
    int s = g_gstart[g], e = g_gstart[g + 1];
    float acc = 0.f;
    for (int n = s; n < e; n++) acc += g_o2[(size_t)n * 128 + f];
    float c = (float)max(e - s, 1);
    g_pool[g * 128 + f] = acc / c;
}
__global__ void k_mlp(const float* __restrict__ Wc1, const float* __restrict__ bc1,
                      const float* __restrict__ Wc2, const float* __restrict__ bc2,
                      float* __restrict__ out) {
    __shared__ float z[64 * 64];
    int tid = threadIdx.x;
    for (int idx = tid; idx < 64 * 64; idx += blockDim.x) {
        int i = idx >> 6, j = idx & 63;
        float acc = bc1[j];
        const float* p = g_pool + i * 128;
        for (int k = 0; k < 128; k++) acc += p[k] * Wc1[k * 64 + j];
        z[idx] = fmaxf(acc, 0.f);
    }
    __syncthreads();
    for (int idx = tid; idx < NG * 4; idx += blockDim.x) {
        int i = idx >> 2, c = idx & 3;
        float acc = bc2[c];
        for (int k = 0; k < 64; k++) acc += z[i * 64 + k] * Wc2[k * 4 + c];
        out[idx] = acc;
    }
}

// ---------------- launch ----------------
extern "C" void kernel_launch(void* const* d_in, const int* in_sizes, int n_in,
                              void* d_out, int out_size) {
    const float* x      = (const float*)d_in[0];
    const int*   ei     = (const int*)d_in[1];
    const int*   batch  = (const int*)d_in[2];
    const float* attn_W = (const float*)d_in[3];
    const float* attn_b = (const float*)d_in[4];
    const float* W1     = (const float*)d_in[5];
    const float* a_src1 = (const float*)d_in[6];
    const float* a_dst1 = (const float*)d_in[7];
    const float* b1     = (const float*)d_in[8];
    const float* W2     = (const float*)d_in[9];
    const float* a_src2 = (const float*)d_in[10];
    const float* a_dst2 = (const float*)d_in[11];
    const float* b2     = (const float*)d_in[12];
    const float* Wc1    = (const float*)d_in[13];
    const float* bc1    = (const float*)d_in[14];
    const float* Wc2    = (const float*)d_in[15];
    const float* bc2    = (const float*)d_in[16];
    float* out = (float*)d_out;

    const int WARP_BLOCKS = (NND * 32 + 255) / 256;   // warp-per-node kernels
    const int EDGE_BLOCKS = (NE + 255) / 256;
    const int MB = (NND + 127) / 128;                 // 235

    k_zero<<<(NND + 255) / 256, 256>>>();
    k_hist<<<EDGE_BLOCKS, 256>>>(ei + NE);
    k_scan1<<<NBLK, 1024>>>();
    k_scan2<<<1, 32>>>();
    k_scan3<<<(NND + 1023) / 1024, 1024>>>();
    k_scatter<<<EDGE_BLOCKS, 256>>>(ei, ei + NE);

    k_cov<<<WARP_BLOCKS, 256>>>(x, W1, attn_W);       // Q + cov logits
    k_gemm_tc<0><<<dim3(2, MB), 256>>>(x, W1, attn_W, attn_b);
    k_alpha1<<<WARP_BLOCKS, 256>>>(a_src1, a_dst1);
    k_agg1<<<WARP_BLOCKS, 256>>>(b1);

    k_gemm_tc<1><<<dim3(1, MB), 256>>>(nullptr, W2, nullptr, nullptr);
    k_alpha2<<<WARP_BLOCKS, 256>>>(a_src2, a_dst2);
    k_agg2<<<WARP_BLOCKS, 256>>>(b2);

    k_gstart<<<1, 128>>>(batch);
    k_pool<<<NG, 128>>>();
    k_mlp<<<1, 256>>>(Wc1, bc1, Wc2, bc2, out);
}